// round 12
// baseline (speedup 1.0000x reference)
#include <cuda_runtime.h>
#include <cuda_bf16.h>
#include <math.h>

// Problem constants
#define BATCH 4
#define SEQ 2048
#define DMODEL 512
#define NHEADS 8
#define DK 64
#define MROWS (BATCH * SEQ)   // 8192

// ---------------- scratch (static device globals; no allocation allowed) ---------
// NOTE: referenced ONLY from device code (host-side use passes the shadow symbol
// and on GB300/ATS writes silently land in host memory — round-2/4 bug).
__device__ float g_Q[BATCH * NHEADS * SEQ * DK];    // head-major [B,H,N,64]
__device__ float g_K[BATCH * NHEADS * SEQ * DK];
__device__ float g_V[BATCH * NHEADS * SEQ * DK];
__device__ float g_attn[MROWS * DMODEL];            // flat [8192,512]

// ---------------- tf32 mma helpers ----------------------------------------------
__device__ __forceinline__ unsigned f2tf32(float x) {
    unsigned u;
    asm("cvt.rna.tf32.f32 %0, %1;" : "=r"(u) : "f"(x));
    return u;
}

__device__ __forceinline__ void mma_tf32(float* c, const unsigned* a, unsigned b0, unsigned b1) {
    asm volatile(
        "mma.sync.aligned.m16n8k8.row.col.f32.tf32.tf32.f32 "
        "{%0,%1,%2,%3}, {%4,%5,%6,%7}, {%8,%9}, {%0,%1,%2,%3};"
        : "+f"(c[0]), "+f"(c[1]), "+f"(c[2]), "+f"(c[3])
        : "r"(a[0]), "r"(a[1]), "r"(a[2]), "r"(a[3]), "r"(b0), "r"(b1));
}

// =================================================================================
// tf32 GEMM (validated round 9: qkv 101us, out ~35us). Unchanged.
// =================================================================================
#define GLDA 36
#define GLDB 136

template <int MODE>
__device__ __forceinline__ void gemm_tf32_body(const float* __restrict__ X,
                                               const float* __restrict__ W,
                                               const float* __restrict__ bias,
                                               float* __restrict__ out)
{
    __shared__ unsigned As[128 * GLDA];
    __shared__ unsigned Bs[32 * GLDB];

    const int tid  = threadIdx.x;
    const int lane = tid & 31;
    const int warp = tid >> 5;
    const int lr   = lane >> 2;   // 0..7
    const int lc   = lane & 3;    // 0..3
    const int warpM = warp >> 1;  // 0..3 -> m offset *32
    const int warpN = warp & 1;   // 0..1 -> n offset *64

    const int rowBase = blockIdx.y * 128;
    const int colBase = blockIdx.x * 128;

    float acc[2][8][4];
#pragma unroll
    for (int mf = 0; mf < 2; mf++)
#pragma unroll
        for (int nf = 0; nf < 8; nf++)
#pragma unroll
            for (int c = 0; c < 4; c++) acc[mf][nf][c] = 0.0f;

    for (int k0 = 0; k0 < DMODEL; k0 += 32) {
        __syncthreads();
#pragma unroll
        for (int i = 0; i < 4; i++) {
            const int e  = i * 256 + tid;
            const int m  = e >> 3;
            const int k4 = (e & 7) << 2;
            const float4 v = *reinterpret_cast<const float4*>(&X[(size_t)(rowBase + m) * DMODEL + k0 + k4]);
            uint4 u;
            u.x = f2tf32(v.x); u.y = f2tf32(v.y); u.z = f2tf32(v.z); u.w = f2tf32(v.w);
            *reinterpret_cast<uint4*>(&As[m * GLDA + k4]) = u;
        }
#pragma unroll
        for (int i = 0; i < 4; i++) {
            const int e  = i * 256 + tid;
            const int k  = e >> 5;
            const int n4 = (e & 31) << 2;
            const float4 v = *reinterpret_cast<const float4*>(&W[(size_t)(k0 + k) * DMODEL + colBase + n4]);
            uint4 u;
            u.x = f2tf32(v.x); u.y = f2tf32(v.y); u.z = f2tf32(v.z); u.w = f2tf32(v.w);
            *reinterpret_cast<uint4*>(&Bs[k * GLDB + n4]) = u;
        }
        __syncthreads();

#pragma unroll
        for (int ks = 0; ks < 4; ks++) {
            unsigned a[2][4];
#pragma unroll
            for (int mf = 0; mf < 2; mf++) {
                const int m0 = warpM * 32 + mf * 16;
                a[mf][0] = As[(m0 + lr    ) * GLDA + ks * 8 + lc];
                a[mf][1] = As[(m0 + lr + 8) * GLDA + ks * 8 + lc];
                a[mf][2] = As[(m0 + lr    ) * GLDA + ks * 8 + lc + 4];
                a[mf][3] = As[(m0 + lr + 8) * GLDA + ks * 8 + lc + 4];
            }
#pragma unroll
            for (int nf = 0; nf < 8; nf++) {
                const int n = warpN * 64 + nf * 8 + lr;
                const unsigned b0 = Bs[(ks * 8 + lc    ) * GLDB + n];
                const unsigned b1 = Bs[(ks * 8 + lc + 4) * GLDB + n];
                mma_tf32(acc[0][nf], a[0], b0, b1);
                mma_tf32(acc[1][nf], a[1], b0, b1);
            }
        }
    }

#pragma unroll
    for (int mf = 0; mf < 2; mf++) {
        const int r0 = rowBase + warpM * 32 + mf * 16 + lr;
        const int r1 = r0 + 8;
#pragma unroll
        for (int nf = 0; nf < 8; nf++) {
            const int col = colBase + warpN * 64 + nf * 8 + 2 * lc;
            const float2 bb = *reinterpret_cast<const float2*>(&bias[col]);
            float2 v0 = make_float2(acc[mf][nf][0] + bb.x, acc[mf][nf][1] + bb.y);
            float2 v1 = make_float2(acc[mf][nf][2] + bb.x, acc[mf][nf][3] + bb.y);
            if (MODE == 0) {
                const int h = col >> 6;
                const int d = col & 63;
                const int b0r = r0 >> 11, n0r = r0 & 2047;
                const int b1r = r1 >> 11, n1r = r1 & 2047;
                *reinterpret_cast<float2*>(&out[(((size_t)(b0r * NHEADS + h) * SEQ) + n0r) * DK + d]) = v0;
                *reinterpret_cast<float2*>(&out[(((size_t)(b1r * NHEADS + h) * SEQ) + n1r) * DK + d]) = v1;
            } else {
                *reinterpret_cast<float2*>(&out[(size_t)r0 * DMODEL + col]) = v0;
                *reinterpret_cast<float2*>(&out[(size_t)r1 * DMODEL + col]) = v1;
            }
        }
    }
}

__global__ void __launch_bounds__(256)
gemm_qkv_kernel(const float* __restrict__ X,
                const float* __restrict__ Wq, const float* __restrict__ Wk,
                const float* __restrict__ Wv,
                const float* __restrict__ bq, const float* __restrict__ bk,
                const float* __restrict__ bv)
{
    const int z = blockIdx.z;
    const float* W = (z == 0) ? Wq : (z == 1) ? Wk : Wv;
    const float* bias = (z == 0) ? bq : (z == 1) ? bk : bv;
    float* out = (z == 0) ? g_Q : (z == 1) ? g_K : g_V;
    gemm_tf32_body<0>(X, W, bias, out);
}

__global__ void __launch_bounds__(256)
gemm_out_kernel(const float* __restrict__ Wo, const float* __restrict__ bo,
                float* __restrict__ out)
{
    gemm_tf32_body<1>(g_attn, Wo, bo, out);
}

// =================================================================================
// Flash attention, tf32 mma. Round 10: BKV 32 -> 64 (halve tile-loop overhead);
// Ks and Ps OVERLAY the same smem buffer (Ks live only in S-phase, Ps only in PV;
// an extra __syncthreads between S-mma and softmax makes aliasing safe).
// smem: KsPs 64*68 + Vt 64*68 = 34,816 B static.
// All frag-read strides are ==4 mod 32 -> conflict-free.
// =================================================================================
#define FBQ 64
#define FBKV 64
#define LDK 68   // 68 % 32 == 4 (Ks and Ps share this stride)
#define LDV 68

__global__ void __launch_bounds__(128)
flash_kernel()
{
    __shared__ unsigned KsPs[FBKV * LDK]; // phase 1: K[kv][d]; phase 2: P[m][kv]
    __shared__ unsigned Vt[DK * LDV];     // V^T[d][kv], tf32 bits

    const int tid  = threadIdx.x;
    const int lane = tid & 31;
    const int warp = tid >> 5;           // 0..3, rows warp*16..+15
    const int wrow = warp * 16;
    const int lr   = lane >> 2;          // 0..7 fragment row
    const int lc   = lane & 3;           // 0..3 fragment col

    const int q0 = blockIdx.x * FBQ;
    const int h  = blockIdx.y;
    const int b  = blockIdx.z;
    const size_t headBase = (size_t)(b * NHEADS + h) * SEQ * DK;
    const float scale = 0.125f;          // 1/sqrt(64)

    // ---- Q fragments in registers (scaled, tf32) --------------------------------
    unsigned qf[8][4];
    {
        const float* Qg = g_Q + headBase + (size_t)(q0 + wrow) * DK;
#pragma unroll
        for (int ks = 0; ks < 8; ks++) {
            const int c0 = ks * 8 + lc;
            qf[ks][0] = f2tf32(Qg[(lr    ) * DK + c0    ] * scale);
            qf[ks][1] = f2tf32(Qg[(lr + 8) * DK + c0    ] * scale);
            qf[ks][2] = f2tf32(Qg[(lr    ) * DK + c0 + 4] * scale);
            qf[ks][3] = f2tf32(Qg[(lr + 8) * DK + c0 + 4] * scale);
        }
    }

    float m0 = -INFINITY, m1 = -INFINITY, l0 = 0.0f, l1 = 0.0f;
    float o[8][4];
#pragma unroll
    for (int nb = 0; nb < 8; nb++)
#pragma unroll
        for (int c = 0; c < 4; c++) o[nb][c] = 0.0f;

    for (int kt = 0; kt < SEQ / FBKV; kt++) {
        const int kv0 = kt * FBKV;

        __syncthreads();   // all warps done with previous Vt reads and Ps region

        // K tile -> KsPs[kv][d] (tf32). 64x64 = 1024 float4, 8 per thread.
        {
            const float* Kg = g_K + headBase + (size_t)kv0 * DK;
#pragma unroll
            for (int i = 0; i < 8; i++) {
                const int e  = i * 128 + tid;
                const int kv = e >> 4;
                const int c4 = (e & 15) << 2;
                const float4 v = *reinterpret_cast<const float4*>(&Kg[kv * DK + c4]);
                uint4 u;
                u.x = f2tf32(v.x); u.y = f2tf32(v.y); u.z = f2tf32(v.z); u.w = f2tf32(v.w);
                *reinterpret_cast<uint4*>(&KsPs[kv * LDK + c4]) = u;
            }
        }
        // V tile -> Vt[d][kv] transposed (tf32). thread: d = tid&63, 8 kv-chunks of 4.
        {
            const float* Vg = g_V + headBase + (size_t)kv0 * DK;
            const int d = tid & 63;
            const int g = tid >> 6;   // 0..1
#pragma unroll
            for (int i = 0; i < 8; i++) {
                const int kvb = (i * 2 + g) * 4;
                uint4 u;
                u.x = f2tf32(Vg[(kvb + 0) * DK + d]);
                u.y = f2tf32(Vg[(kvb + 1) * DK + d]);
                u.z = f2tf32(Vg[(kvb + 2) * DK + d]);
                u.w = f2tf32(Vg[(kvb + 3) * DK + d]);
                *reinterpret_cast<uint4*>(&Vt[d * LDV + kvb]) = u;
            }
        }
        __syncthreads();

        // ---- S = Q K^T : 8 k-steps x 8 n-blocks ---------------------------------
        float s[8][4];
#pragma unroll
        for (int nb = 0; nb < 8; nb++)
#pragma unroll
            for (int c = 0; c < 4; c++) s[nb][c] = 0.0f;

#pragma unroll
        for (int ks = 0; ks < 8; ks++) {
#pragma unroll
            for (int nb = 0; nb < 8; nb++) {
                const unsigned b0 = KsPs[(nb * 8 + lr) * LDK + ks * 8 + lc];
                const unsigned b1 = KsPs[(nb * 8 + lr) * LDK + ks * 8 + lc + 4];
                mma_tf32(s[nb], qf[ks], b0, b1);
            }
        }

        __syncthreads();   // every warp finished reading Ks -> safe to overwrite as Ps

        // ---- online softmax (two row-halves: lr and lr+8) -----------------------
#pragma unroll
        for (int hh = 0; hh < 2; hh++) {
            const int ci = hh * 2;   // c indices ci, ci+1 belong to this row half
            float vmax = s[0][ci];
#pragma unroll
            for (int nb = 0; nb < 8; nb++)
                vmax = fmaxf(vmax, fmaxf(s[nb][ci], s[nb][ci + 1]));
            vmax = fmaxf(vmax, __shfl_xor_sync(0xffffffffu, vmax, 1));
            vmax = fmaxf(vmax, __shfl_xor_sync(0xffffffffu, vmax, 2));

            float& m = hh ? m1 : m0;
            float& l = hh ? l1 : l0;
            const float m_new = fmaxf(m, vmax);
            const float corr  = __expf(m - m_new);

            float sum = 0.0f;
            const int prow = wrow + lr + hh * 8;
#pragma unroll
            for (int nb = 0; nb < 8; nb++) {
                const float p0 = __expf(s[nb][ci]     - m_new);
                const float p1 = __expf(s[nb][ci + 1] - m_new);
                sum += p0 + p1;
                uint2 pp;
                pp.x = f2tf32(p0);
                pp.y = f2tf32(p1);
                *reinterpret_cast<uint2*>(&KsPs[prow * LDK + nb * 8 + 2 * lc]) = pp;
            }
            sum += __shfl_xor_sync(0xffffffffu, sum, 1);
            sum += __shfl_xor_sync(0xffffffffu, sum, 2);

            l = l * corr + sum;
            m = m_new;
#pragma unroll
            for (int nb = 0; nb < 8; nb++) {
                o[nb][ci]     *= corr;
                o[nb][ci + 1] *= corr;
            }
        }
        __syncwarp();   // Ps rows are warp-private: order STS before LDS in-warp

        // ---- O += P V : 8 k-steps x 8 n-blocks ----------------------------------
#pragma unroll
        for (int ks = 0; ks < 8; ks++) {
            unsigned a[4];
            a[0] = KsPs[(wrow + lr    ) * LDK + ks * 8 + lc];
            a[1] = KsPs[(wrow + lr + 8) * LDK + ks * 8 + lc];
            a[2] = KsPs[(wrow + lr    ) * LDK + ks * 8 + lc + 4];
            a[3] = KsPs[(wrow + lr + 8) * LDK + ks * 8 + lc + 4];
#pragma unroll
            for (int nb = 0; nb < 8; nb++) {
                const unsigned b0 = Vt[(nb * 8 + lr) * LDV + ks * 8 + lc];
                const unsigned b1 = Vt[(nb * 8 + lr) * LDV + ks * 8 + lc + 4];
                mma_tf32(o[nb], a, b0, b1);
            }
        }
    }

    // ---- epilogue: normalize and write g_attn [8192, 512] ----------------------
    const float inv0 = 1.0f / l0;
    const float inv1 = 1.0f / l1;
    const int row0 = b * SEQ + q0 + wrow + lr;
    const int row1 = row0 + 8;
#pragma unroll
    for (int nb = 0; nb < 8; nb++) {
        const int col = h * DK + nb * 8 + 2 * lc;
        float2 w0 = make_float2(o[nb][0] * inv0, o[nb][1] * inv0);
        float2 w1 = make_float2(o[nb][2] * inv1, o[nb][3] * inv1);
        *reinterpret_cast<float2*>(&g_attn[(size_t)row0 * DMODEL + col]) = w0;
        *reinterpret_cast<float2*>(&g_attn[(size_t)row1 * DMODEL + col]) = w1;
    }
}

// =================================================================================
// launch
// =================================================================================
extern "C" void kernel_launch(void* const* d_in, const int* in_sizes, int n_in,
                              void* d_out, int out_size)
{
    const float* x  = (const float*)d_in[0];
    const float* Wq = (const float*)d_in[1];
    const float* bq = (const float*)d_in[2];
    const float* Wk = (const float*)d_in[3];
    const float* bk = (const float*)d_in[4];
    const float* Wv = (const float*)d_in[5];
    const float* bv = (const float*)d_in[6];
    const float* Wo = (const float*)d_in[7];
    const float* bo = (const float*)d_in[8];
    float* out = (float*)d_out;

    // 1) QKV projections (tf32 mma) into head-major scratch
    dim3 gQKV(DMODEL / 128, MROWS / 128, 3);
    gemm_qkv_kernel<<<gQKV, 256>>>(x, Wq, Wk, Wv, bq, bk, bv);

    // 2) flash attention (tf32 tensor cores) -> g_attn
    dim3 gF(SEQ / FBQ, NHEADS, BATCH);
    flash_kernel<<<gF, 128>>>();

    // 3) output projection (tf32 mma) -> d_out
    dim3 gO(DMODEL / 128, MROWS / 128);
    gemm_out_kernel<<<gO, 256>>>(Wo, bo, out);
}

// round 14
// speedup vs baseline: 1.6625x; 1.6625x over previous
#include <cuda_runtime.h>
#include <cuda_bf16.h>
#include <math.h>

// Problem constants
#define BATCH 4
#define SEQ 2048
#define DMODEL 512
#define NHEADS 8
#define DK 64
#define MROWS (BATCH * SEQ)   // 8192

// ---------------- scratch (static device globals; no allocation allowed) ---------
// NOTE: referenced ONLY from device code (host-side use passes the shadow symbol
// and on GB300/ATS writes silently land in host memory — round-2/4 bug).
// g_Q/g_K/g_V hold tf32-RNA-ROUNDED fp32 values (rounded in the QKV GEMM epilogue)
// so the flash kernel can feed raw bits to HMMA with no mainloop converts.
__device__ float g_Q[BATCH * NHEADS * SEQ * DK];    // head-major [B,H,N,64]
__device__ float g_K[BATCH * NHEADS * SEQ * DK];
__device__ float g_V[BATCH * NHEADS * SEQ * DK];
__device__ float g_attn[MROWS * DMODEL];            // flat [8192,512]

// ---------------- tf32 mma helpers ----------------------------------------------
__device__ __forceinline__ unsigned f2tf32(float x) {
    unsigned u;
    asm("cvt.rna.tf32.f32 %0, %1;" : "=r"(u) : "f"(x));
    return u;
}

__device__ __forceinline__ float f2tf32f(float x) {   // RNA-round, keep as float
    unsigned u;
    asm("cvt.rna.tf32.f32 %0, %1;" : "=r"(u) : "f"(x));
    return __uint_as_float(u);
}

__device__ __forceinline__ void mma_tf32(float* c, const unsigned* a, unsigned b0, unsigned b1) {
    asm volatile(
        "mma.sync.aligned.m16n8k8.row.col.f32.tf32.tf32.f32 "
        "{%0,%1,%2,%3}, {%4,%5,%6,%7}, {%8,%9}, {%0,%1,%2,%3};"
        : "+f"(c[0]), "+f"(c[1]), "+f"(c[2]), "+f"(c[3])
        : "r"(a[0]), "r"(a[1]), "r"(a[2]), "r"(a[3]), "r"(b0), "r"(b1));
}

// ---------------- cp.async helpers -----------------------------------------------
__device__ __forceinline__ void cp_async16(unsigned smem_addr, const void* gptr) {
    asm volatile("cp.async.cg.shared.global [%0], [%1], 16;" :: "r"(smem_addr), "l"(gptr));
}
__device__ __forceinline__ void cp_async_commit() {
    asm volatile("cp.async.commit_group;");
}
__device__ __forceinline__ void cp_async_wait_all() {
    asm volatile("cp.async.wait_group 0;");
}

// =================================================================================
// tf32 GEMM (validated round 9: qkv 101us, out ~35us).
// MODE 0 change (round 14): epilogue RNA-rounds outputs to tf32 grid so flash can
// consume raw bits. MODE 1 (final output) stays full fp32.
// =================================================================================
#define GLDA 36
#define GLDB 136

template <int MODE>
__device__ __forceinline__ void gemm_tf32_body(const float* __restrict__ X,
                                               const float* __restrict__ W,
                                               const float* __restrict__ bias,
                                               float* __restrict__ out)
{
    __shared__ unsigned As[128 * GLDA];
    __shared__ unsigned Bs[32 * GLDB];

    const int tid  = threadIdx.x;
    const int lane = tid & 31;
    const int warp = tid >> 5;
    const int lr   = lane >> 2;   // 0..7
    const int lc   = lane & 3;    // 0..3
    const int warpM = warp >> 1;  // 0..3 -> m offset *32
    const int warpN = warp & 1;   // 0..1 -> n offset *64

    const int rowBase = blockIdx.y * 128;
    const int colBase = blockIdx.x * 128;

    float acc[2][8][4];
#pragma unroll
    for (int mf = 0; mf < 2; mf++)
#pragma unroll
        for (int nf = 0; nf < 8; nf++)
#pragma unroll
            for (int c = 0; c < 4; c++) acc[mf][nf][c] = 0.0f;

    for (int k0 = 0; k0 < DMODEL; k0 += 32) {
        __syncthreads();
#pragma unroll
        for (int i = 0; i < 4; i++) {
            const int e  = i * 256 + tid;
            const int m  = e >> 3;
            const int k4 = (e & 7) << 2;
            const float4 v = *reinterpret_cast<const float4*>(&X[(size_t)(rowBase + m) * DMODEL + k0 + k4]);
            uint4 u;
            u.x = f2tf32(v.x); u.y = f2tf32(v.y); u.z = f2tf32(v.z); u.w = f2tf32(v.w);
            *reinterpret_cast<uint4*>(&As[m * GLDA + k4]) = u;
        }
#pragma unroll
        for (int i = 0; i < 4; i++) {
            const int e  = i * 256 + tid;
            const int k  = e >> 5;
            const int n4 = (e & 31) << 2;
            const float4 v = *reinterpret_cast<const float4*>(&W[(size_t)(k0 + k) * DMODEL + colBase + n4]);
            uint4 u;
            u.x = f2tf32(v.x); u.y = f2tf32(v.y); u.z = f2tf32(v.z); u.w = f2tf32(v.w);
            *reinterpret_cast<uint4*>(&Bs[k * GLDB + n4]) = u;
        }
        __syncthreads();

#pragma unroll
        for (int ks = 0; ks < 4; ks++) {
            unsigned a[2][4];
#pragma unroll
            for (int mf = 0; mf < 2; mf++) {
                const int m0 = warpM * 32 + mf * 16;
                a[mf][0] = As[(m0 + lr    ) * GLDA + ks * 8 + lc];
                a[mf][1] = As[(m0 + lr + 8) * GLDA + ks * 8 + lc];
                a[mf][2] = As[(m0 + lr    ) * GLDA + ks * 8 + lc + 4];
                a[mf][3] = As[(m0 + lr + 8) * GLDA + ks * 8 + lc + 4];
            }
#pragma unroll
            for (int nf = 0; nf < 8; nf++) {
                const int n = warpN * 64 + nf * 8 + lr;
                const unsigned b0 = Bs[(ks * 8 + lc    ) * GLDB + n];
                const unsigned b1 = Bs[(ks * 8 + lc + 4) * GLDB + n];
                mma_tf32(acc[0][nf], a[0], b0, b1);
                mma_tf32(acc[1][nf], a[1], b0, b1);
            }
        }
    }

#pragma unroll
    for (int mf = 0; mf < 2; mf++) {
        const int r0 = rowBase + warpM * 32 + mf * 16 + lr;
        const int r1 = r0 + 8;
#pragma unroll
        for (int nf = 0; nf < 8; nf++) {
            const int col = colBase + warpN * 64 + nf * 8 + 2 * lc;
            const float2 bb = *reinterpret_cast<const float2*>(&bias[col]);
            float2 v0 = make_float2(acc[mf][nf][0] + bb.x, acc[mf][nf][1] + bb.y);
            float2 v1 = make_float2(acc[mf][nf][2] + bb.x, acc[mf][nf][3] + bb.y);
            if (MODE == 0) {
                // RNA-round to tf32 grid: flash consumes these raw as tf32 operands
                v0.x = f2tf32f(v0.x); v0.y = f2tf32f(v0.y);
                v1.x = f2tf32f(v1.x); v1.y = f2tf32f(v1.y);
                const int h = col >> 6;
                const int d = col & 63;
                const int b0r = r0 >> 11, n0r = r0 & 2047;
                const int b1r = r1 >> 11, n1r = r1 & 2047;
                *reinterpret_cast<float2*>(&out[(((size_t)(b0r * NHEADS + h) * SEQ) + n0r) * DK + d]) = v0;
                *reinterpret_cast<float2*>(&out[(((size_t)(b1r * NHEADS + h) * SEQ) + n1r) * DK + d]) = v1;
            } else {
                *reinterpret_cast<float2*>(&out[(size_t)r0 * DMODEL + col]) = v0;
                *reinterpret_cast<float2*>(&out[(size_t)r1 * DMODEL + col]) = v1;
            }
        }
    }
}

__global__ void __launch_bounds__(256)
gemm_qkv_kernel(const float* __restrict__ X,
                const float* __restrict__ Wq, const float* __restrict__ Wk,
                const float* __restrict__ Wv,
                const float* __restrict__ bq, const float* __restrict__ bk,
                const float* __restrict__ bv)
{
    const int z = blockIdx.z;
    const float* W = (z == 0) ? Wq : (z == 1) ? Wk : Wv;
    const float* bias = (z == 0) ? bq : (z == 1) ? bk : bv;
    float* out = (z == 0) ? g_Q : (z == 1) ? g_K : g_V;
    gemm_tf32_body<0>(X, W, bias, out);
}

__global__ void __launch_bounds__(256)
gemm_out_kernel(const float* __restrict__ Wo, const float* __restrict__ bo,
                float* __restrict__ out)
{
    gemm_tf32_body<1>(g_attn, Wo, bo, out);
}

// =================================================================================
// Flash attention, tf32 mma, round 14:
//  - r13 structure (cp.async double-buffered K/V, one __syncthreads/iter) KEPT.
//  - Numerics restored to r9 level: K/V arrive pre-RNA-rounded from the QKV GEMM
//    (raw bits are exact tf32), Q fragments RNA-rounded after scaling, Ps stores
//    RNA-rounded. No converts in the K/V path of the mainloop.
//  - Layouts: Ks[kv][d] LDK=68, Vs[kv][d] LDV=72, Ps[m][kv] LDP=36 (all
//    conflict-free for their frag read patterns).
//  smem: 2*32*68*4 + 2*32*72*4 + 64*36*4 = 45,056 B static.
// =================================================================================
#define FBQ 64
#define FBKV 32
#define LDK 68   // 68 % 32 == 4
#define LDV 72   // 72 % 32 == 8
#define LDP 36   // 36 % 32 == 4

__global__ void __launch_bounds__(128)
flash_kernel()
{
    __shared__ unsigned Ks[2][FBKV * LDK];  // K[kv][d], pre-rounded tf32 bits
    __shared__ unsigned Vs[2][FBKV * LDV];  // V[kv][d], pre-rounded tf32 bits
    __shared__ unsigned Ps[FBQ * LDP];      // P[m][kv], tf32 bits

    const int tid  = threadIdx.x;
    const int lane = tid & 31;
    const int warp = tid >> 5;           // 0..3, rows warp*16..+15
    const int wrow = warp * 16;
    const int lr   = lane >> 2;          // 0..7 fragment row
    const int lc   = lane & 3;           // 0..3 fragment col

    const int q0 = blockIdx.x * FBQ;
    const int h  = blockIdx.y;
    const int b  = blockIdx.z;
    const size_t headBase = (size_t)(b * NHEADS + h) * SEQ * DK;
    const float scale = 0.125f;          // 1/sqrt(64)

    const unsigned ksBase0 = (unsigned)__cvta_generic_to_shared(&Ks[0][0]);
    const unsigned ksBase1 = (unsigned)__cvta_generic_to_shared(&Ks[1][0]);
    const unsigned vsBase0 = (unsigned)__cvta_generic_to_shared(&Vs[0][0]);
    const unsigned vsBase1 = (unsigned)__cvta_generic_to_shared(&Vs[1][0]);

    const float* Kg_head = g_K + headBase;
    const float* Vg_head = g_V + headBase;

    // ---- Q fragments in registers (scale by 1/8, RNA to tf32) -------------------
    unsigned qf[8][4];
    {
        const float* Qg = g_Q + headBase + (size_t)(q0 + wrow) * DK;
#pragma unroll
        for (int ks = 0; ks < 8; ks++) {
            const int c0 = ks * 8 + lc;
            qf[ks][0] = f2tf32(Qg[(lr    ) * DK + c0    ] * scale);
            qf[ks][1] = f2tf32(Qg[(lr + 8) * DK + c0    ] * scale);
            qf[ks][2] = f2tf32(Qg[(lr    ) * DK + c0 + 4] * scale);
            qf[ks][3] = f2tf32(Qg[(lr + 8) * DK + c0 + 4] * scale);
        }
    }

    // ---- prologue: prefetch tile 0 into buffer 0 --------------------------------
    {
        const float* Kg = Kg_head;
        const float* Vg = Vg_head;
#pragma unroll
        for (int i = 0; i < 4; i++) {
            const int c = i * 128 + tid;
            const int row = c >> 4, ch = c & 15;
            cp_async16(ksBase0 + (unsigned)(row * LDK + ch * 4) * 4u, Kg + row * DK + ch * 4);
        }
#pragma unroll
        for (int i = 0; i < 4; i++) {
            const int c = i * 128 + tid;
            const int row = c >> 4, ch = c & 15;
            cp_async16(vsBase0 + (unsigned)(row * LDV + ch * 4) * 4u, Vg + row * DK + ch * 4);
        }
        cp_async_commit();
    }

    float m0 = -INFINITY, m1 = -INFINITY, l0 = 0.0f, l1 = 0.0f;
    float o[8][4];
#pragma unroll
    for (int nb = 0; nb < 8; nb++)
#pragma unroll
        for (int c = 0; c < 4; c++) o[nb][c] = 0.0f;

    for (int kt = 0; kt < SEQ / FBKV; kt++) {
        const int buf = kt & 1;

        cp_async_wait_all();   // this tile's K/V landed (this thread's groups)
        __syncthreads();       // visible to all warps; other buffer fully consumed

        // prefetch next tile into the other buffer (overlaps all compute below)
        if (kt + 1 < SEQ / FBKV) {
            const float* Kg = Kg_head + (size_t)(kt + 1) * FBKV * DK;
            const float* Vg = Vg_head + (size_t)(kt + 1) * FBKV * DK;
            const unsigned kb = buf ? ksBase0 : ksBase1;
            const unsigned vb = buf ? vsBase0 : vsBase1;
#pragma unroll
            for (int i = 0; i < 4; i++) {
                const int c = i * 128 + tid;
                const int row = c >> 4, ch = c & 15;
                cp_async16(kb + (unsigned)(row * LDK + ch * 4) * 4u, Kg + row * DK + ch * 4);
            }
#pragma unroll
            for (int i = 0; i < 4; i++) {
                const int c = i * 128 + tid;
                const int row = c >> 4, ch = c & 15;
                cp_async16(vb + (unsigned)(row * LDV + ch * 4) * 4u, Vg + row * DK + ch * 4);
            }
            cp_async_commit();
        }

        // ---- S = Q K^T : 8 k-steps x 4 n-blocks ---------------------------------
        float s[4][4];
#pragma unroll
        for (int nb = 0; nb < 4; nb++)
#pragma unroll
            for (int c = 0; c < 4; c++) s[nb][c] = 0.0f;

#pragma unroll
        for (int ks = 0; ks < 8; ks++) {
#pragma unroll
            for (int nb = 0; nb < 4; nb++) {
                const unsigned b0 = Ks[buf][(nb * 8 + lr) * LDK + ks * 8 + lc];
                const unsigned b1 = Ks[buf][(nb * 8 + lr) * LDK + ks * 8 + lc + 4];
                mma_tf32(s[nb], qf[ks], b0, b1);
            }
        }

        // ---- online softmax (two row-halves: lr and lr+8) -----------------------
#pragma unroll
        for (int hh = 0; hh < 2; hh++) {
            const int ci = hh * 2;
            float vmax = s[0][ci];
#pragma unroll
            for (int nb = 0; nb < 4; nb++)
                vmax = fmaxf(vmax, fmaxf(s[nb][ci], s[nb][ci + 1]));
            vmax = fmaxf(vmax, __shfl_xor_sync(0xffffffffu, vmax, 1));
            vmax = fmaxf(vmax, __shfl_xor_sync(0xffffffffu, vmax, 2));

            float& m = hh ? m1 : m0;
            float& l = hh ? l1 : l0;
            const float m_new = fmaxf(m, vmax);
            const float corr  = __expf(m - m_new);

            float sum = 0.0f;
            const int prow = wrow + lr + hh * 8;
#pragma unroll
            for (int nb = 0; nb < 4; nb++) {
                const float p0 = __expf(s[nb][ci]     - m_new);
                const float p1 = __expf(s[nb][ci + 1] - m_new);
                sum += p0 + p1;
                uint2 pp;
                pp.x = f2tf32(p0);     // RNA — truncation here cost 1e-3 in r13
                pp.y = f2tf32(p1);
                *reinterpret_cast<uint2*>(&Ps[prow * LDP + nb * 8 + 2 * lc]) = pp;
            }
            sum += __shfl_xor_sync(0xffffffffu, sum, 1);
            sum += __shfl_xor_sync(0xffffffffu, sum, 2);

            l = l * corr + sum;
            m = m_new;
#pragma unroll
            for (int nb = 0; nb < 8; nb++) {
                o[nb][ci]     *= corr;
                o[nb][ci + 1] *= corr;
            }
        }
        __syncwarp();   // Ps rows are warp-private: order STS before LDS in-warp

        // ---- O += P V : 4 k-steps x 8 n-blocks (B straight from Vs[kv][d]) ------
#pragma unroll
        for (int ks = 0; ks < 4; ks++) {
            unsigned a[4];
            a[0] = Ps[(wrow + lr    ) * LDP + ks * 8 + lc];
            a[1] = Ps[(wrow + lr + 8) * LDP + ks * 8 + lc];
            a[2] = Ps[(wrow + lr    ) * LDP + ks * 8 + lc + 4];
            a[3] = Ps[(wrow + lr + 8) * LDP + ks * 8 + lc + 4];
#pragma unroll
            for (int nb = 0; nb < 8; nb++) {
                const unsigned b0 = Vs[buf][(ks * 8 + lc    ) * LDV + nb * 8 + lr];
                const unsigned b1 = Vs[buf][(ks * 8 + lc + 4) * LDV + nb * 8 + lr];
                mma_tf32(o[nb], a, b0, b1);
            }
        }
    }

    // ---- epilogue: normalize and write g_attn [8192, 512] ----------------------
    const float inv0 = 1.0f / l0;
    const float inv1 = 1.0f / l1;
    const int row0 = b * SEQ + q0 + wrow + lr;
    const int row1 = row0 + 8;
#pragma unroll
    for (int nb = 0; nb < 8; nb++) {
        const int col = h * DK + nb * 8 + 2 * lc;
        float2 w0 = make_float2(o[nb][0] * inv0, o[nb][1] * inv0);
        float2 w1 = make_float2(o[nb][2] * inv1, o[nb][3] * inv1);
        *reinterpret_cast<float2*>(&g_attn[(size_t)row0 * DMODEL + col]) = w0;
        *reinterpret_cast<float2*>(&g_attn[(size_t)row1 * DMODEL + col]) = w1;
    }
}

// =================================================================================
// launch
// =================================================================================
extern "C" void kernel_launch(void* const* d_in, const int* in_sizes, int n_in,
                              void* d_out, int out_size)
{
    const float* x  = (const float*)d_in[0];
    const float* Wq = (const float*)d_in[1];
    const float* bq = (const float*)d_in[2];
    const float* Wk = (const float*)d_in[3];
    const float* bk = (const float*)d_in[4];
    const float* Wv = (const float*)d_in[5];
    const float* bv = (const float*)d_in[6];
    const float* Wo = (const float*)d_in[7];
    const float* bo = (const float*)d_in[8];
    float* out = (float*)d_out;

    // 1) QKV projections (tf32 mma) into head-major scratch (tf32-rounded values)
    dim3 gQKV(DMODEL / 128, MROWS / 128, 3);
    gemm_qkv_kernel<<<gQKV, 256>>>(x, Wq, Wk, Wv, bq, bk, bv);

    // 2) flash attention (tf32 mma, cp.async double-buffered) -> g_attn
    dim3 gF(SEQ / FBQ, NHEADS, BATCH);
    flash_kernel<<<gF, 128>>>();

    // 3) output projection (tf32 mma) -> d_out
    dim3 gO(DMODEL / 128, MROWS / 128);
    gemm_out_kernel<<<gO, 256>>>(Wo, bo, out);
}